// round 17
// baseline (speedup 1.0000x reference)
#include <cuda_runtime.h>
#include <cuda_bf16.h>

// SSIM preservation loss: 1 - mean(ssim_map(clean, adversarial))
// 4-channel transform: convolve s=x+y, d=x-y, s^2, d^2. Separable 11x11
// Gaussian. R16: ALL-SCALAR math (FFMA-imm rt=1 == packed pipe time, zero
// weight registers) to fit 85 regs -> 3 CTAs/SM (24 warps) via
// __launch_bounds__(256,3). Rings are scalar floats; 2 rows per barrier.

#define IMG_W 512
#define IMG_H 512
#define ROWS_PER_BLOCK 16
#define STRIPS (IMG_H / ROWS_PER_BLOCK)   // 32
#define NPLANES 96                        // 32 batch * 3 channels
#define NBLOCKS (NPLANES * STRIPS)        // 3072
#define NTHREADS 256
#define TOTAL_PIX 25165824.0              // 32*3*512*512

// 1D Gaussian weights, sigma=1.5, normalized (immediates in FFMA).
#define KW0 0.00102838f
#define KW1 0.00759876f
#define KW2 0.03600077f
#define KW3 0.10936070f
#define KW4 0.21300560f
#define KW5 0.26601170f
#define C1X2 2.0e-4f
#define C2X2 1.8e-3f

__device__ double g_partials[NBLOCKS];
__device__ unsigned int g_ticket = 0;

__device__ __forceinline__ float frcp(float x) {
    float r; asm("rcp.approx.f32 %0, %1;" : "=f"(r) : "f"(x)); return r;
}

__device__ __forceinline__ float kwt(int tt) {
    return (tt == 0 || tt == 10) ? KW0 :
           (tt == 1 || tt == 9)  ? KW1 :
           (tt == 2 || tt == 8)  ? KW2 :
           (tt == 3 || tt == 7)  ? KW3 :
           (tt == 4 || tt == 6)  ? KW4 : KW5;
}

__global__ void __launch_bounds__(NTHREADS, 3)
ssim_main(const float* __restrict__ X, const float* __restrict__ Y,
          float* __restrict__ out) {
    const int b     = blockIdx.x;
    const int plane = b >> 5;        // / STRIPS
    const int strip = b & 31;        // % STRIPS
    const int r0    = strip * ROWS_PER_BLOCK;
    const int t     = threadIdx.x;
    const int c0    = t * 2;

    const float* __restrict__ px = X + (size_t)plane * (IMG_H * IMG_W);
    const float* __restrict__ py = Y + (size_t)plane * (IMG_H * IMG_W);

    // 4 row buffers (2 row-pairs, alternating): index = 8 + col.
    __shared__ float vbuf[4][4][528];
    __shared__ float warpsum[8];
    __shared__ bool  is_last;
    __shared__ double sd[NTHREADS];

    if (t < 4) {
        #pragma unroll
        for (int bb = 0; bb < 4; bb++) {
            #pragma unroll
            for (int i = 0; i < 8; i++) {
                vbuf[bb][t][i] = 0.0f;
                vbuf[bb][t][520 + i] = 0.0f;
            }
        }
    }

    // Scalar register rings: 11 rows x 2 cols, channels s = x+y, d = x-y.
    float rsx[11], rsy[11], rdx[11], rdy[11];

    // Prime slots 0..9 with input rows r0-5 .. r0+4 (zero outside image).
    #pragma unroll
    for (int k = 0; k < 10; k++) {
        int ir = r0 - 5 + k;
        float2 vx = make_float2(0.f, 0.f), vy = make_float2(0.f, 0.f);
        if ((unsigned)ir < (unsigned)IMG_H) {
            vx = *(const float2*)(px + ir * IMG_W + c0);
            vy = *(const float2*)(py + ir * IMG_W + c0);
        }
        rsx[k] = vx.x + vy.x;  rsy[k] = vx.y + vy.y;
        rdx[k] = vx.x - vy.x;  rdy[k] = vx.y - vy.y;
    }

    // Two-row pipeline: cur = row r0+5, nxt = row r0+6.
    float2 curx = make_float2(0.f, 0.f), cury = make_float2(0.f, 0.f);
    float2 nxtx = make_float2(0.f, 0.f), nxty = make_float2(0.f, 0.f);
    {
        int ira = r0 + 5, irb = r0 + 6;
        if (ira < IMG_H) {
            curx = *(const float2*)(px + ira * IMG_W + c0);
            cury = *(const float2*)(py + ira * IMG_W + c0);
        }
        if (irb < IMG_H) {
            nxtx = *(const float2*)(px + irb * IMG_W + c0);
            nxty = *(const float2*)(py + irb * IMG_W + c0);
        }
    }

    float acc0 = 0.0f, acc1 = 0.0f;

    #pragma unroll
    for (int rp = 0; rp < ROWS_PER_BLOCK / 2; rp++) {
        const int r  = 2 * rp;
        const int pb = rp & 1;           // buffer pair select: {0,1} or {2,3}

        // ---- vertical pass for the two rows of this pair ----
        #pragma unroll
        for (int sub = 0; sub < 2; sub++) {
            const int rr = r + sub;
            // push current row (r0+rr+5) into ring slot (rr+10)%11
            {
                const int sl = (rr + 10) % 11;
                float2 ax = sub ? nxtx : curx;
                float2 ay = sub ? nxty : cury;
                rsx[sl] = ax.x + ay.x;  rsy[sl] = ax.y + ay.y;
                rdx[sl] = ax.x - ay.x;  rdy[sl] = ax.y - ay.y;
            }
            // refill the consumed pipeline slot with row (r0+rr+7)
            {
                int irn = r0 + rr + 7;
                float2 lx = make_float2(0.f, 0.f), ly = make_float2(0.f, 0.f);
                if ((unsigned)irn < (unsigned)IMG_H) {
                    lx = *(const float2*)(px + irn * IMG_W + c0);
                    ly = *(const float2*)(py + irn * IMG_W + c0);
                }
                if (sub == 0) { curx = lx; cury = ly; }
                else          { nxtx = lx; nxty = ly; }
            }
            // 11-tap vertical conv (scalar FFMA-imm; squares on the fly)
            float msx, msy, mdx_, mdy_, esx, esy, edx_, edy_;
            {
                const int s0 = rr % 11;
                float sx = rsx[s0], sy = rsy[s0], dx = rdx[s0], dy = rdy[s0];
                msx  = KW0 * sx;        msy  = KW0 * sy;
                mdx_ = KW0 * dx;        mdy_ = KW0 * dy;
                esx  = KW0 * (sx * sx); esy  = KW0 * (sy * sy);
                edx_ = KW0 * (dx * dx); edy_ = KW0 * (dy * dy);
            }
            #pragma unroll
            for (int tt = 1; tt < 11; tt++) {
                const int sl = (rr + tt) % 11;
                const float w = kwt(tt);
                float sx = rsx[sl], sy = rsy[sl], dx = rdx[sl], dy = rdy[sl];
                msx  = fmaf(w, sx, msx);        msy  = fmaf(w, sy, msy);
                mdx_ = fmaf(w, dx, mdx_);       mdy_ = fmaf(w, dy, mdy_);
                esx  = fmaf(w, sx * sx, esx);   esy  = fmaf(w, sy * sy, esy);
                edx_ = fmaf(w, dx * dx, edx_);  edy_ = fmaf(w, dy * dy, edy_);
            }
            const int buf = 2 * pb + sub;
            *(float2*)(&vbuf[buf][0][8 + c0]) = make_float2(msx, msy);
            *(float2*)(&vbuf[buf][1][8 + c0]) = make_float2(mdx_, mdy_);
            *(float2*)(&vbuf[buf][2][8 + c0]) = make_float2(esx, esy);
            *(float2*)(&vbuf[buf][3][8 + c0]) = make_float2(edx_, edy_);
        }

        __syncthreads();   // one barrier per 2 rows

        // ---- horizontal pass + SSIM for both rows (scalar FFMA-imm) ----
        #pragma unroll
        for (int sub = 0; sub < 2; sub++) {
            const int buf = 2 * pb + sub;
            float h0[4], h1[4];
            #pragma unroll
            for (int q = 0; q < 4; q++) {
                const float2* vb = (const float2*)(&vbuf[buf][q][8 + c0 - 6]);
                float2 f0 = vb[0];   // v[-6], v[-5]
                float2 f1 = vb[1];   // v[-4], v[-3]
                float2 f2 = vb[2];   // v[-2], v[-1]
                float2 f3 = vb[3];   // v[0],  v[1]
                float2 f4 = vb[4];   // v[2],  v[3]
                float2 f5 = vb[5];   // v[4],  v[5]
                float2 f6 = vb[6];   // v[6],  v[7]

                float p0 = KW0 * f0.y;
                p0 = fmaf(KW1, f1.x, p0);
                p0 = fmaf(KW2, f1.y, p0);
                p0 = fmaf(KW3, f2.x, p0);
                p0 = fmaf(KW4, f2.y, p0);
                p0 = fmaf(KW5, f3.x, p0);
                p0 = fmaf(KW4, f3.y, p0);
                p0 = fmaf(KW3, f4.x, p0);
                p0 = fmaf(KW2, f4.y, p0);
                p0 = fmaf(KW1, f5.x, p0);
                p0 = fmaf(KW0, f5.y, p0);

                float p1 = KW0 * f1.x;
                p1 = fmaf(KW1, f1.y, p1);
                p1 = fmaf(KW2, f2.x, p1);
                p1 = fmaf(KW3, f2.y, p1);
                p1 = fmaf(KW4, f3.x, p1);
                p1 = fmaf(KW5, f3.y, p1);
                p1 = fmaf(KW4, f4.x, p1);
                p1 = fmaf(KW3, f4.y, p1);
                p1 = fmaf(KW2, f5.x, p1);
                p1 = fmaf(KW1, f5.y, p1);
                p1 = fmaf(KW0, f6.x, p1);

                h0[q] = p0;
                h1[q] = p1;
            }

            // ---- SSIM, x4-scaled (bit-identical quotient), per pixel ----
            {
                float A = h0[0] * h0[0];
                float B = h0[1] * h0[1];
                float P2 = A + B;
                float Q2 = A - B;
                float SE = h0[2] + h0[3];
                float DE = h0[2] - h0[3];
                float R2 = SE - P2;
                float T2 = DE - Q2;
                float num = (Q2 + C1X2) * (T2 + C2X2);
                float den = (P2 + C1X2) * (R2 + C2X2);
                acc0 = fmaf(num, frcp(den), acc0);
            }
            {
                float A = h1[0] * h1[0];
                float B = h1[1] * h1[1];
                float P2 = A + B;
                float Q2 = A - B;
                float SE = h1[2] + h1[3];
                float DE = h1[2] - h1[3];
                float R2 = SE - P2;
                float T2 = DE - Q2;
                float num = (Q2 + C1X2) * (T2 + C2X2);
                float den = (P2 + C1X2) * (R2 + C2X2);
                acc1 = fmaf(num, frcp(den), acc1);
            }
        }
    }

    float acc = acc0 + acc1;

    // ---- deterministic block reduction ----
    #pragma unroll
    for (int off = 16; off > 0; off >>= 1)
        acc += __shfl_xor_sync(0xffffffffu, acc, off);
    if ((t & 31) == 0) warpsum[t >> 5] = acc;
    __syncthreads();
    if (t == 0) {
        float s = 0.0f;
        #pragma unroll
        for (int i = 0; i < 8; i++) s += warpsum[i];
        g_partials[b] = (double)s;
    }

    // ---- fused finalize: last block sums all partials (deterministic) ----
    __threadfence();
    if (t == 0) {
        unsigned int old = atomicAdd(&g_ticket, 1u);
        is_last = (old == NBLOCKS - 1);
    }
    __syncthreads();
    if (is_last) {
        double sm = 0.0;
        for (int i = t; i < NBLOCKS; i += NTHREADS) sm += g_partials[i];
        sd[t] = sm;
        __syncthreads();
        #pragma unroll
        for (int off = NTHREADS / 2; off > 0; off >>= 1) {
            if (t < off) sd[t] += sd[t + off];
            __syncthreads();
        }
        if (t == 0) {
            out[0] = (float)(1.0 - sd[0] / TOTAL_PIX);
            g_ticket = 0;   // reset for next graph replay
        }
    }
}

extern "C" void kernel_launch(void* const* d_in, const int* in_sizes, int n_in,
                              void* d_out, int out_size) {
    const float* clean = (const float*)d_in[0];
    const float* adv   = (const float*)d_in[1];
    ssim_main<<<NBLOCKS, NTHREADS>>>(clean, adv, (float*)d_out);
}